// round 2
// baseline (speedup 1.0000x reference)
#include <cuda_runtime.h>
#include <math.h>

// Problem constants
constexpr int B = 2, L = 2048, D = 1024, H = 16, DK = 64;
constexpr int M = B * L;                         // 4096 rows
constexpr int OUT_ELEMS = B * L * D;             // 4,194,304
constexpr long long ATTN_ELEMS = (long long)B * H * L * L;  // 134,217,728

// Device scratch (static — no runtime allocation allowed)
__device__ float g_Q[B * H * L * DK];   // (b,h,l,dk)
__device__ float g_K[B * H * L * DK];
__device__ float g_V[B * H * L * DK];
__device__ float g_O[B * L * H * DK];   // (b,l, h*dv) — row-major for FC
__device__ float g_X[B * L * D];        // FC output + residual, pre-LN
__device__ float g_rsum[B * H * L];     // softmax row sums

// ---------------------------------------------------------------------------
// 128x128x8 SGEMM, 256 threads, 8x8 per thread.
// MODE 0/1/2: C = A @ W, scatter-store to g_Q/g_K/g_V in (b,h,l,dk) layout.
// MODE 3:     C = g_O @ W + resid, store to g_X.
// ---------------------------------------------------------------------------
template <int MODE>
__global__ void __launch_bounds__(256) gemm128(const float* __restrict__ Ain,
                                               const float* __restrict__ W,
                                               const float* __restrict__ resid) {
  __shared__ float As[8][132];
  __shared__ float Ws[8][132];
  const float* A = (MODE == 3) ? (const float*)g_O : Ain;

  const int tid = threadIdx.x;
  const int tx = tid & 15, ty = tid >> 4;
  const int m0 = blockIdx.y * 128, n0 = blockIdx.x * 128;
  const int a_r = tid >> 1;            // 0..127
  const int a_c = (tid & 1) * 4;       // 0 or 4
  const int w_r = tid >> 5;            // 0..7
  const int w_c = (tid & 31) * 4;      // 0..124

  float acc[8][8];
#pragma unroll
  for (int i = 0; i < 8; i++)
#pragma unroll
    for (int j = 0; j < 8; j++) acc[i][j] = 0.f;

  for (int kt = 0; kt < D; kt += 8) {
    float4 av = *(const float4*)&A[(size_t)(m0 + a_r) * D + kt + a_c];
    float4 wv = *(const float4*)&W[(size_t)(kt + w_r) * D + n0 + w_c];
    As[a_c + 0][a_r] = av.x;
    As[a_c + 1][a_r] = av.y;
    As[a_c + 2][a_r] = av.z;
    As[a_c + 3][a_r] = av.w;
    *(float4*)&Ws[w_r][w_c] = wv;
    __syncthreads();
#pragma unroll
    for (int kk = 0; kk < 8; kk++) {
      float a[8], b[8];
      *(float4*)&a[0] = *(const float4*)&As[kk][ty * 8];
      *(float4*)&a[4] = *(const float4*)&As[kk][ty * 8 + 4];
      *(float4*)&b[0] = *(const float4*)&Ws[kk][tx * 8];
      *(float4*)&b[4] = *(const float4*)&Ws[kk][tx * 8 + 4];
#pragma unroll
      for (int i = 0; i < 8; i++)
#pragma unroll
        for (int j = 0; j < 8; j++) acc[i][j] = fmaf(a[i], b[j], acc[i][j]);
    }
    __syncthreads();
  }

  if (MODE <= 2) {
    float* dst = (MODE == 0) ? g_Q : (MODE == 1) ? g_K : g_V;
#pragma unroll
    for (int i = 0; i < 8; i++) {
      int m = m0 + ty * 8 + i;
      int bb = m >> 11;            // m / L
      int l = m & (L - 1);
      int n = n0 + tx * 8;
      int hh = n >> 6;             // stays constant across the 8 j's (8-aligned)
      int dk = n & 63;
      float* p = &dst[(((size_t)(bb * H + hh) * L) + l) * DK + dk];
      *(float4*)p = make_float4(acc[i][0], acc[i][1], acc[i][2], acc[i][3]);
      *(float4*)(p + 4) = make_float4(acc[i][4], acc[i][5], acc[i][6], acc[i][7]);
    }
  } else {
#pragma unroll
    for (int i = 0; i < 8; i++) {
      int m = m0 + ty * 8 + i;
      int n = n0 + tx * 8;
      float4 r0 = *(const float4*)&resid[(size_t)m * D + n];
      float4 r1 = *(const float4*)&resid[(size_t)m * D + n + 4];
      *(float4*)&g_X[(size_t)m * D + n] = make_float4(
          acc[i][0] + r0.x, acc[i][1] + r0.y, acc[i][2] + r0.z, acc[i][3] + r0.w);
      *(float4*)&g_X[(size_t)m * D + n + 4] = make_float4(
          acc[i][4] + r1.x, acc[i][5] + r1.y, acc[i][6] + r1.z, acc[i][7] + r1.w);
    }
  }
}

// ---------------------------------------------------------------------------
// Fused attention: per (b, h, 128-row q-tile), loop over 64-wide k-tiles.
// Computes E = exp(QK^T/8) with mask, writes unnormalized E to attn output,
// accumulates row sums and O = E @ V, then stores O / rowsum.
// ---------------------------------------------------------------------------
__global__ void __launch_bounds__(256) attn_kernel(const int* __restrict__ mask,
                                                   float* __restrict__ attnE) {
  extern __shared__ float sm[];
  float* QsT = sm;                  // [64][132], d-major: QsT[d][r]
  float* KsT = sm + 64 * 132;       // [64][68],  d-major: KsT[d][c]
  float* Vs = KsT + 64 * 68;        // [64][68],  Vs[c][dv]
  float* EsT = Vs + 64 * 68;        // [64][132], k-major: EsT[kk][r]
  __shared__ float rsum_s[128];

  const int tid = threadIdx.x;
  const int tx = tid & 15, ty = tid >> 4;
  const int b = blockIdx.z, h = blockIdx.y;
  const int q0 = blockIdx.x * 128;
  const int bh = b * H + h;
  const float* Qb = g_Q + ((size_t)bh * L + q0) * DK;
  const float* Kb = g_K + (size_t)bh * L * DK;
  const float* Vb = g_V + (size_t)bh * L * DK;

  // Load Q tile (128x64) transposed
#pragma unroll
  for (int it = 0; it < 8; it++) {
    int o = (tid + it * 256) * 4;   // 0..8188
    int r = o >> 6, d = o & 63;
    float4 v4 = *(const float4*)&Qb[o];
    QsT[(d + 0) * 132 + r] = v4.x;
    QsT[(d + 1) * 132 + r] = v4.y;
    QsT[(d + 2) * 132 + r] = v4.z;
    QsT[(d + 3) * 132 + r] = v4.w;
  }

  float rs[8];
  float acc_o[8][4];
#pragma unroll
  for (int i = 0; i < 8; i++) {
    rs[i] = 0.f;
#pragma unroll
    for (int j = 0; j < 4; j++) acc_o[i][j] = 0.f;
  }

  for (int k0 = 0; k0 < L; k0 += 64) {
    __syncthreads();  // previous EV readers done before overwriting tiles
    // Load K (transposed) and V tiles (64x64 each)
#pragma unroll
    for (int it = 0; it < 4; it++) {
      int o = (tid + it * 256) * 4;  // 0..4092
      int c = o >> 6, d = o & 63;
      float4 kv = *(const float4*)&Kb[(size_t)(k0 + c) * DK + d];
      KsT[(d + 0) * 68 + c] = kv.x;
      KsT[(d + 1) * 68 + c] = kv.y;
      KsT[(d + 2) * 68 + c] = kv.z;
      KsT[(d + 3) * 68 + c] = kv.w;
      float4 vv = *(const float4*)&Vb[(size_t)(k0 + c) * DK + d];
      *(float4*)&Vs[c * 68 + d] = vv;
    }
    __syncthreads();

    // S tile: 128x64, 8x4 per thread
    float acc_s[8][4];
#pragma unroll
    for (int i = 0; i < 8; i++)
#pragma unroll
      for (int j = 0; j < 4; j++) acc_s[i][j] = 0.f;

#pragma unroll 8
    for (int d = 0; d < 64; d++) {
      float a[8], bb4[4];
      *(float4*)&a[0] = *(const float4*)&QsT[d * 132 + ty * 8];
      *(float4*)&a[4] = *(const float4*)&QsT[d * 132 + ty * 8 + 4];
      *(float4*)&bb4[0] = *(const float4*)&KsT[d * 68 + tx * 4];
#pragma unroll
      for (int i = 0; i < 8; i++)
#pragma unroll
        for (int j = 0; j < 4; j++) acc_s[i][j] = fmaf(a[i], bb4[j], acc_s[i][j]);
    }

    // Epilogue: mask, exp, write E (smem transposed + optional gmem), rowsum
#pragma unroll
    for (int i = 0; i < 8; i++) {
      int qr = q0 + ty * 8 + i;
      int4 mv = *(const int4*)&mask[((size_t)b * L + qr) * L + k0 + tx * 4];
      int mm[4] = {mv.x, mv.y, mv.z, mv.w};
      float e[4];
#pragma unroll
      for (int j = 0; j < 4; j++) {
        float s = acc_s[i][j] * 0.125f;
        float ev = (mm[j] != 0) ? __expf(fminf(s, 60.f)) : 0.f;
        e[j] = ev;
        rs[i] += ev;
        EsT[(tx * 4 + j) * 132 + ty * 8 + i] = ev;
      }
      if (attnE) {
        *(float4*)&attnE[((size_t)bh * L + qr) * L + k0 + tx * 4] =
            make_float4(e[0], e[1], e[2], e[3]);
      }
    }
    __syncthreads();

    // O += E @ V
#pragma unroll 8
    for (int kk = 0; kk < 64; kk++) {
      float a[8], bb4[4];
      *(float4*)&a[0] = *(const float4*)&EsT[kk * 132 + ty * 8];
      *(float4*)&a[4] = *(const float4*)&EsT[kk * 132 + ty * 8 + 4];
      *(float4*)&bb4[0] = *(const float4*)&Vs[kk * 68 + tx * 4];
#pragma unroll
      for (int i = 0; i < 8; i++)
#pragma unroll
        for (int j = 0; j < 4; j++) acc_o[i][j] = fmaf(a[i], bb4[j], acc_o[i][j]);
    }
  }

  // Reduce row sums across the 16 tx lanes (lanes 0..15 / 16..31 are separate rows)
#pragma unroll
  for (int i = 0; i < 8; i++) {
    float v = rs[i];
    v += __shfl_xor_sync(0xffffffffu, v, 8);
    v += __shfl_xor_sync(0xffffffffu, v, 4);
    v += __shfl_xor_sync(0xffffffffu, v, 2);
    v += __shfl_xor_sync(0xffffffffu, v, 1);
    if (tx == 0) rsum_s[ty * 8 + i] = v;
  }
  __syncthreads();
  if (tid < 128) g_rsum[(size_t)bh * L + q0 + tid] = rsum_s[tid];

  // Store normalized O in (b, l, h*dv) layout
#pragma unroll
  for (int i = 0; i < 8; i++) {
    float inv = 1.f / rsum_s[ty * 8 + i];
    int qr = q0 + ty * 8 + i;
    *(float4*)&g_O[((size_t)b * L + qr) * (H * DK) + h * DK + tx * 4] =
        make_float4(acc_o[i][0] * inv, acc_o[i][1] * inv,
                    acc_o[i][2] * inv, acc_o[i][3] * inv);
  }
}

// Normalize attn rows by 1/rowsum (one block per (bh, row))
__global__ void __launch_bounds__(256) attn_norm(float* __restrict__ attnE) {
  const int row = blockIdx.x;
  const int bh = blockIdx.y;
  const float inv = 1.f / g_rsum[(size_t)bh * L + row];
  float* p = attnE + ((size_t)bh * L + row) * L;
#pragma unroll
  for (int it = 0; it < 2; it++) {
    int o = (threadIdx.x + it * 256) * 4;
    float4 v = *(const float4*)&p[o];
    v.x *= inv; v.y *= inv; v.z *= inv; v.w *= inv;
    *(float4*)&p[o] = v;
  }
}

// LayerNorm over last dim (one block per row)
__global__ void __launch_bounds__(256) ln_kernel(const float* __restrict__ gamma,
                                                 const float* __restrict__ beta,
                                                 float* __restrict__ out) {
  const int row = blockIdx.x;
  const int tid = threadIdx.x;
  const float* x = g_X + (size_t)row * D;
  float4 v = *(const float4*)&x[tid * 4];
  float s = v.x + v.y + v.z + v.w;
  float s2 = v.x * v.x + v.y * v.y + v.z * v.z + v.w * v.w;
#pragma unroll
  for (int off = 16; off; off >>= 1) {
    s += __shfl_xor_sync(0xffffffffu, s, off);
    s2 += __shfl_xor_sync(0xffffffffu, s2, off);
  }
  __shared__ float ws[8], ws2[8];
  __shared__ float mean_s, rstd_s;
  int wid = tid >> 5, lid = tid & 31;
  if (lid == 0) { ws[wid] = s; ws2[wid] = s2; }
  __syncthreads();
  if (tid == 0) {
    float S = 0.f, S2 = 0.f;
#pragma unroll
    for (int w = 0; w < 8; w++) { S += ws[w]; S2 += ws2[w]; }
    float mu = S * (1.f / D);
    float var = S2 * (1.f / D) - mu * mu;
    mean_s = mu;
    rstd_s = rsqrtf(var + 1e-6f);
  }
  __syncthreads();
  float mu = mean_s, rstd = rstd_s;
  float4 g4 = *(const float4*)&gamma[tid * 4];
  float4 b4 = *(const float4*)&beta[tid * 4];
  float4 o;
  o.x = (v.x - mu) * rstd * g4.x + b4.x;
  o.y = (v.y - mu) * rstd * g4.y + b4.y;
  o.z = (v.z - mu) * rstd * g4.z + b4.z;
  o.w = (v.w - mu) * rstd * g4.w + b4.w;
  *(float4*)&out[(size_t)row * D + tid * 4] = o;
}

extern "C" void kernel_launch(void* const* d_in, const int* in_sizes, int n_in,
                              void* d_out, int out_size) {
  const float* q = (const float*)d_in[0];
  const float* k = (const float*)d_in[1];
  const float* v = (const float*)d_in[2];
  const int* mask = (const int*)d_in[3];
  const float* wq = (const float*)d_in[4];
  const float* wk = (const float*)d_in[5];
  const float* wv = (const float*)d_in[6];
  const float* wfc = (const float*)d_in[7];
  const float* lng = (const float*)d_in[8];
  const float* lnb = (const float*)d_in[9];
  (void)in_sizes; (void)n_in;

  float* out = (float*)d_out;
  float* attn = nullptr;
  if ((long long)out_size >= (long long)OUT_ELEMS + ATTN_ELEMS)
    attn = out + OUT_ELEMS;

  dim3 gemm_grid(D / 128, M / 128);
  gemm128<0><<<gemm_grid, 256>>>(q, wq, nullptr);
  gemm128<1><<<gemm_grid, 256>>>(k, wk, nullptr);
  gemm128<2><<<gemm_grid, 256>>>(v, wv, nullptr);

  cudaFuncSetAttribute(attn_kernel, cudaFuncAttributeMaxDynamicSharedMemorySize,
                       102400);
  attn_kernel<<<dim3(L / 128, H, B), 256, 102400>>>(mask, attn);
  if (attn) attn_norm<<<dim3(L, B * H), 256>>>(attn);

  gemm128<3><<<gemm_grid, 256>>>(nullptr, wfc, q);
  ln_kernel<<<M, 256>>>(lng, lnb, out);
}

// round 6
// speedup vs baseline: 1.8506x; 1.8506x over previous
#include <cuda_runtime.h>
#include <cuda_bf16.h>
#include <cstdint>

constexpr int B = 2, L = 2048, D = 1024, H = 16;
constexpr int M = B * L;
constexpr int OUT_ELEMS = B * L * D;

// ---- static device scratch ----
__device__ __align__(16) __nv_bfloat16 g_qh[M * D], g_ql[M * D];
__device__ __align__(16) __nv_bfloat16 g_kh[M * D], g_kl[M * D], g_vbf[M * D];
__device__ __align__(16) __nv_bfloat16 g_wqh[D * D], g_wql[D * D];
__device__ __align__(16) __nv_bfloat16 g_wkh[D * D], g_wkl[D * D];
__device__ __align__(16) __nv_bfloat16 g_wvh[D * D], g_wfh[D * D];
__device__ __align__(16) __nv_bfloat16 g_Qh[M * D], g_Ql[M * D];
__device__ __align__(16) __nv_bfloat16 g_Kh[M * D], g_Kl[M * D];
__device__ __align__(16) __nv_bfloat16 g_Vt[M * D];   // (b,h,dv,l)
__device__ __align__(16) __nv_bfloat16 g_Obf[M * D];  // (b,l,h*dv)
__device__ __align__(16) float g_X[M * D];
__device__ uint32_t g_mbits[(size_t)B * L * (L / 32)];

// ---- helpers (plain sm_103-legal PTX only) ----
__device__ __forceinline__ uint32_t s2u(const void* p) {
  uint32_t a;
  asm("{ .reg .u64 t; cvta.to.shared.u64 t, %1; cvt.u32.u64 %0, t; }" : "=r"(a) : "l"(p));
  return a;
}
#define CPA(dst, src) asm volatile("cp.async.cg.shared.global [%0], [%1], 16;" :: "r"(dst), "l"(src))
#define CPC() asm volatile("cp.async.commit_group;" ::: "memory")
#define CPW(n) asm volatile("cp.async.wait_group %0;" :: "n"(n) : "memory")
__device__ __forceinline__ void ldm4(uint32_t* r, uint32_t a) {
  asm volatile("ldmatrix.sync.aligned.m8n8.x4.shared.b16 {%0,%1,%2,%3}, [%4];"
               : "=r"(r[0]), "=r"(r[1]), "=r"(r[2]), "=r"(r[3]) : "r"(a));
}
__device__ __forceinline__ void mma_bf(float* d, const uint32_t* a, const uint32_t* b) {
  asm volatile(
      "mma.sync.aligned.m16n8k16.row.col.f32.bf16.bf16.f32 "
      "{%0,%1,%2,%3},{%4,%5,%6,%7},{%8,%9},{%0,%1,%2,%3};"
      : "+f"(d[0]), "+f"(d[1]), "+f"(d[2]), "+f"(d[3])
      : "r"(a[0]), "r"(a[1]), "r"(a[2]), "r"(a[3]), "r"(b[0]), "r"(b[1]));
}
__device__ __forceinline__ uint32_t packbf(float a, float b) {
  __nv_bfloat162 p = __halves2bfloat162(__float2bfloat16(a), __float2bfloat16(b));
  return *(uint32_t*)&p;
}

// ---- prep kernels ----
__global__ void __launch_bounds__(256) cvt_split(const float* __restrict__ in,
    __nv_bfloat16* __restrict__ hi, __nv_bfloat16* __restrict__ lo) {
  size_t i = (size_t)blockIdx.x * 1024 + threadIdx.x * 4;
  float4 v = *(const float4*)(in + i);
  float a[4] = {v.x, v.y, v.z, v.w};
  uint32_t ph[2], pl[2];
#pragma unroll
  for (int j = 0; j < 2; j++) {
    float x0 = a[j * 2], x1 = a[j * 2 + 1];
    __nv_bfloat16 h0 = __float2bfloat16(x0), h1 = __float2bfloat16(x1);
    ph[j] = packbf(x0, x1);
    pl[j] = packbf(x0 - __bfloat162float(h0), x1 - __bfloat162float(h1));
  }
  *(uint2*)(hi + i) = make_uint2(ph[0], ph[1]);
  *(uint2*)(lo + i) = make_uint2(pl[0], pl[1]);
}
__global__ void __launch_bounds__(256) cvt1(const float* __restrict__ in,
                                            __nv_bfloat16* __restrict__ o) {
  size_t i = (size_t)blockIdx.x * 1024 + threadIdx.x * 4;
  float4 v = *(const float4*)(in + i);
  *(uint2*)(o + i) = make_uint2(packbf(v.x, v.y), packbf(v.z, v.w));
}
template <bool SPLIT>
__global__ void __launch_bounds__(256) wtrans(const float* __restrict__ w,
    __nv_bfloat16* __restrict__ th, __nv_bfloat16* __restrict__ tl) {
  __shared__ float t[32][33];
  int tx = threadIdx.x & 31, ty = threadIdx.x >> 5;
  int x0 = blockIdx.x * 32, y0 = blockIdx.y * 32;
#pragma unroll
  for (int i = 0; i < 4; i++)
    t[ty + i * 8][tx] = w[(size_t)(y0 + ty + i * 8) * D + x0 + tx];
  __syncthreads();
#pragma unroll
  for (int i = 0; i < 4; i++) {
    float v = t[tx][ty + i * 8];
    __nv_bfloat16 h = __float2bfloat16(v);
    size_t o = (size_t)(x0 + ty + i * 8) * D + y0 + tx;
    th[o] = h;
    if (SPLIT) tl[o] = __float2bfloat16(v - __bfloat162float(h));
  }
}
__global__ void __launch_bounds__(256) mask_pack(const int* __restrict__ mask,
                                                 uint32_t* __restrict__ bits) {
  size_t w = (size_t)blockIdx.x * 256 + threadIdx.x;
  const int4* p = (const int4*)mask + w * 8;
  uint32_t v = 0;
#pragma unroll
  for (int i = 0; i < 8; i++) {
    int4 m = p[i];
    v |= (m.x != 0 ? 1u : 0u) << (i * 4);
    v |= (m.y != 0 ? 1u : 0u) << (i * 4 + 1);
    v |= (m.z != 0 ? 1u : 0u) << (i * 4 + 2);
    v |= (m.w != 0 ? 1u : 0u) << (i * 4 + 3);
  }
  bits[w] = v;
}

// ---- HMMA GEMM: 128x128 tile, BK=32, cp.async double-buffered ----
// MODE 0=Q(split,scale) 1=K(split) 2=V(transpose out) 3=FC(residual)
template <int MODE>
__global__ void __launch_bounds__(256) mmk(const __nv_bfloat16* __restrict__ Ah,
    const __nv_bfloat16* __restrict__ Al, const __nv_bfloat16* __restrict__ Bh,
    const __nv_bfloat16* __restrict__ Bl, const float* __restrict__ resid) {
  constexpr bool SPLIT = (MODE <= 1);
  constexpr int NT = SPLIT ? 4 : 2;
  extern __shared__ char sm[];
  const uint32_t sb = s2u(sm);
  const int tid = threadIdx.x, lane = tid & 31, wid = tid >> 5;
  const int wy = wid >> 1, wx = wid & 1;
  const int m0 = blockIdx.y * 128, n0 = blockIdx.x * 128;
  const int lr = (lane & 7) + ((lane >> 3) & 1) * 8, lc = (lane >> 4) * 8;
  const int r0 = lane >> 2, c0 = 2 * (lane & 3);

  float acc[2][8][4];
#pragma unroll
  for (int i = 0; i < 2; i++)
#pragma unroll
    for (int j = 0; j < 8; j++)
#pragma unroll
      for (int t = 0; t < 4; t++) acc[i][j][t] = 0.f;

  auto issue = [&](int kc, int buf) {
    uint32_t bs = sb + buf * NT * 10240;
#pragma unroll
    for (int i = 0; i < 2; i++) {
      int idx = tid + i * 256, row = idx >> 2, seg = idx & 3;
      uint32_t d0 = bs + row * 80 + seg * 16;
      size_t sa = (size_t)(m0 + row) * D + kc * 32 + seg * 8;
      size_t sg = (size_t)(n0 + row) * D + kc * 32 + seg * 8;
      CPA(d0, Ah + sa);
      CPA(d0 + 10240, Bh + sg);
      if (SPLIT) { CPA(d0 + 20480, Al + sa); CPA(d0 + 30720, Bl + sg); }
    }
    CPC();
  };

  issue(0, 0);
  for (int kc = 0; kc < 32; kc++) {
    if (kc < 31) { issue(kc + 1, (kc + 1) & 1); CPW(1); } else { CPW(0); }
    __syncthreads();
    uint32_t bs = sb + (kc & 1) * NT * 10240;
#pragma unroll
    for (int ks = 0; ks < 2; ks++) {
      uint32_t aH[2][4], aL[2][4], bH[4][4], bL[4][4];
#pragma unroll
      for (int mi = 0; mi < 2; mi++) {
        uint32_t o = ((wy * 32 + mi * 16 + lr) * 40 + ks * 16 + lc) * 2;
        ldm4(aH[mi], bs + o);
        if (SPLIT) ldm4(aL[mi], bs + 20480 + o);
      }
#pragma unroll
      for (int ni = 0; ni < 4; ni++) {
        uint32_t o = ((wx * 64 + ni * 16 + lr) * 40 + ks * 16 + lc) * 2;
        ldm4(bH[ni], bs + 10240 + o);
        if (SPLIT) ldm4(bL[ni], bs + 30720 + o);
      }
#pragma unroll
      for (int mi = 0; mi < 2; mi++)
#pragma unroll
        for (int nj = 0; nj < 8; nj++) {
          uint32_t bb2[2] = {bH[nj >> 1][nj & 1], bH[nj >> 1][(nj & 1) + 2]};
          mma_bf(acc[mi][nj], aH[mi], bb2);
          if (SPLIT) {
            uint32_t bl2[2] = {bL[nj >> 1][nj & 1], bL[nj >> 1][(nj & 1) + 2]};
            mma_bf(acc[mi][nj], aH[mi], bl2);
            mma_bf(acc[mi][nj], aL[mi], bb2);
          }
        }
    }
    __syncthreads();
  }

  if (MODE <= 1) {
    __nv_bfloat16* DH = (MODE == 0) ? g_Qh : g_Kh;
    __nv_bfloat16* DL = (MODE == 0) ? g_Ql : g_Kl;
    const float sc = (MODE == 0) ? 0.125f : 1.f;
#pragma unroll
    for (int mi = 0; mi < 2; mi++)
#pragma unroll
      for (int nj = 0; nj < 8; nj++)
#pragma unroll
        for (int hf = 0; hf < 2; hf++) {
          int mrow = m0 + wy * 32 + mi * 16 + r0 + hf * 8;
          int ncol = n0 + wx * 64 + nj * 8 + c0;
          float v0 = acc[mi][nj][hf * 2] * sc, v1 = acc[mi][nj][hf * 2 + 1] * sc;
          __nv_bfloat16 h0 = __float2bfloat16(v0), h1 = __float2bfloat16(v1);
          int bb = mrow >> 11, ll = mrow & 2047, hh = ncol >> 6, dk = ncol & 63;
          size_t o = (((size_t)bb * H + hh) * L + ll) * 64 + dk;
          *(uint32_t*)(DH + o) = packbf(v0, v1);
          *(uint32_t*)(DL + o) = packbf(v0 - __bfloat162float(h0), v1 - __bfloat162float(h1));
        }
  } else if (MODE == 3) {
#pragma unroll
    for (int mi = 0; mi < 2; mi++)
#pragma unroll
      for (int nj = 0; nj < 8; nj++)
#pragma unroll
        for (int hf = 0; hf < 2; hf++) {
          int mrow = m0 + wy * 32 + mi * 16 + r0 + hf * 8;
          int ncol = n0 + wx * 64 + nj * 8 + c0;
          size_t o = (size_t)mrow * D + ncol;
          float2 rv = *(const float2*)(resid + o);
          *(float2*)(g_X + o) = make_float2(acc[mi][nj][hf * 2] + rv.x,
                                            acc[mi][nj][hf * 2 + 1] + rv.y);
        }
  } else {  // V: stage bf16 tile, transpose-write to g_Vt
    __nv_bfloat16* Cs = (__nv_bfloat16*)sm;
#pragma unroll
    for (int mi = 0; mi < 2; mi++)
#pragma unroll
      for (int nj = 0; nj < 8; nj++)
#pragma unroll
        for (int hf = 0; hf < 2; hf++) {
          int rl = wy * 32 + mi * 16 + r0 + hf * 8;
          int cl = wx * 64 + nj * 8 + c0;
          *(uint32_t*)(Cs + rl * 132 + cl) =
              packbf(acc[mi][nj][hf * 2], acc[mi][nj][hf * 2 + 1]);
        }
    __syncthreads();
    int bb = m0 >> 11, l0g = m0 & 2047;
#pragma unroll
    for (int rep = 0; rep < 8; rep++) {
      int col = rep * 16 + (tid >> 4);
      int ls = (tid & 15) * 8;
      int ncol = n0 + col, hh = ncol >> 6, dv = ncol & 63;
      union { unsigned short s[8]; uint4 u; } tmp;
#pragma unroll
      for (int j = 0; j < 8; j++) tmp.s[j] = ((unsigned short*)Cs)[(ls + j) * 132 + col];
      *(uint4*)(g_Vt + (((size_t)bb * H + hh) * 64 + dv) * L + l0g + ls) = tmp.u;
    }
  }
}

// ---- fused attention (HMMA) ----
// smem map (disjoint; the R4 bug was oVT1 overlapping oKL1 by 1024B):
// KH0 [0,18432) KL0 [18432,36864) VT0 [36864,54272)
// KH1 [54272,72704) KL1 [72704,91136) VT1 [91136,108544)
// ES  [108544,143360)  QL [143360,161792)  PS [161792,162816)  SI [162816,163328)
constexpr int oKH0 = 0, oKL0 = 18432, oVT0 = 36864;
constexpr int oKH1 = 54272, oKL1 = 72704, oVT1 = 91136;
constexpr int oES = 108544;
constexpr int oQL = 143360;
constexpr int oPS = 161792, oSI = 162816;
constexpr int ATTN_SMEM = 163328;

__global__ void __launch_bounds__(256) attn_tc(float* __restrict__ attnE) {
  extern __shared__ char sm[];
  const uint32_t sb = s2u(sm);
  const int tid = threadIdx.x, lane = tid & 31, wid = tid >> 5;
  const int wy = wid >> 1, wx = wid & 1;
  const int b = blockIdx.z, h = blockIdx.y, q0 = blockIdx.x * 128, bh = b * H + h;
  const int lr = (lane & 7) + ((lane >> 3) & 1) * 8, lc = (lane >> 4) * 8;
  const int r0 = lane >> 2, c0 = 2 * (lane & 3);

  {  // stage Q: hi into ES area (row stride 144B), lo into its slot
    const __nv_bfloat16* Qh = g_Qh + ((size_t)bh * L + q0) * 64;
    const __nv_bfloat16* Ql = g_Ql + ((size_t)bh * L + q0) * 64;
#pragma unroll
    for (int i = 0; i < 4; i++) {
      int idx = tid + i * 256, row = idx >> 3, seg = idx & 7;
      *(uint4*)(sm + oES + row * 144 + seg * 16) = *(const uint4*)(Qh + (size_t)row * 64 + seg * 8);
      *(uint4*)(sm + oQL + row * 144 + seg * 16) = *(const uint4*)(Ql + (size_t)row * 64 + seg * 8);
    }
  }
  __syncthreads();

  auto issue = [&](int kc, int buf) {
    uint32_t oK = sb + (buf ? oKH1 : oKH0);
    uint32_t oKl = sb + (buf ? oKL1 : oKL0);
    uint32_t oV = sb + (buf ? oVT1 : oVT0);
    const __nv_bfloat16* Kh = g_Kh + ((size_t)bh * L + kc * 128) * 64;
    const __nv_bfloat16* Kl = g_Kl + ((size_t)bh * L + kc * 128) * 64;
    const __nv_bfloat16* Vt = g_Vt + (size_t)bh * 64 * L + kc * 128;
#pragma unroll
    for (int i = 0; i < 4; i++) {
      int idx = tid + i * 256, row = idx >> 3, seg = idx & 7;
      CPA(oK + row * 144 + seg * 16, Kh + (size_t)row * 64 + seg * 8);
      CPA(oKl + row * 144 + seg * 16, Kl + (size_t)row * 64 + seg * 8);
    }
#pragma unroll
    for (int i = 0; i < 4; i++) {  // full 64x128 V tile
      int idx = tid + i * 256, row = idx >> 4, seg = idx & 15;
      CPA(oV + row * 272 + seg * 16, Vt + (size_t)row * L + seg * 8);
    }
    CPC();
  };
  issue(0, 0);

  uint32_t qh[2][4][4];
#pragma unroll
  for (int mi = 0; mi < 2; mi++)
#pragma unroll
    for (int ks = 0; ks < 4; ks++)
      ldm4(qh[mi][ks], sb + oES + ((wy * 32 + mi * 16 + lr) * 72 + ks * 16 + lc) * 2);

  float acc_o[2][4][4];
#pragma unroll
  for (int i = 0; i < 2; i++)
#pragma unroll
    for (int j = 0; j < 4; j++)
#pragma unroll
      for (int t = 0; t < 4; t++) acc_o[i][j][t] = 0.f;
  float rs[4] = {0.f, 0.f, 0.f, 0.f};

  for (int kc = 0; kc < 16; kc++) {
    if (kc < 15) { issue(kc + 1, (kc + 1) & 1); CPW(1); } else { CPW(0); }
    __syncthreads();
    uint32_t bK = sb + ((kc & 1) ? oKH1 : oKH0);
    uint32_t bKl = sb + ((kc & 1) ? oKL1 : oKL0);
    uint32_t bV = sb + ((kc & 1) ? oVT1 : oVT0);

    float sacc[2][8][4];
#pragma unroll
    for (int i = 0; i < 2; i++)
#pragma unroll
      for (int j = 0; j < 8; j++)
#pragma unroll
        for (int t = 0; t < 4; t++) sacc[i][j][t] = 0.f;

#pragma unroll
    for (int ks = 0; ks < 4; ks++) {
      uint32_t bh4[4][4], bl4[4][4], ql4[2][4];
#pragma unroll
      for (int ni = 0; ni < 4; ni++) {
        uint32_t o = ((wx * 64 + ni * 16 + lr) * 72 + ks * 16 + lc) * 2;
        ldm4(bh4[ni], bK + o);
        ldm4(bl4[ni], bKl + o);
      }
#pragma unroll
      for (int mi = 0; mi < 2; mi++)
        ldm4(ql4[mi], sb + oQL + ((wy * 32 + mi * 16 + lr) * 72 + ks * 16 + lc) * 2);
#pragma unroll
      for (int mi = 0; mi < 2; mi++)
#pragma unroll
        for (int nj = 0; nj < 8; nj++) {
          uint32_t bb2[2] = {bh4[nj >> 1][nj & 1], bh4[nj >> 1][(nj & 1) + 2]};
          uint32_t bl2[2] = {bl4[nj >> 1][nj & 1], bl4[nj >> 1][(nj & 1) + 2]};
          mma_bf(sacc[mi][nj], qh[mi][ks], bb2);
          mma_bf(sacc[mi][nj], qh[mi][ks], bl2);
          mma_bf(sacc[mi][nj], ql4[mi], bb2);
        }
    }

    // epilogue: mask, exp, fp32->gmem, bf16->smem, rowsum
#pragma unroll
    for (int mi = 0; mi < 2; mi++) {
      uint32_t wm[2][2];
#pragma unroll
      for (int hf = 0; hf < 2; hf++) {
        int qr = q0 + wy * 32 + mi * 16 + r0 + hf * 8;
        size_t mo = ((size_t)b * L + qr) * 64 + kc * 4 + wx * 2;
        wm[hf][0] = g_mbits[mo];
        wm[hf][1] = g_mbits[mo + 1];
      }
#pragma unroll
      for (int nj = 0; nj < 8; nj++)
#pragma unroll
        for (int hf = 0; hf < 2; hf++) {
          int rl = wy * 32 + mi * 16 + r0 + hf * 8;
          int qr = q0 + rl;
          int colL = wx * 64 + nj * 8 + c0;
          uint32_t w = wm[hf][nj >> 2];
          int bp = (nj * 8 + c0) & 31;
          float e0 = ((w >> bp) & 1u) ? __expf(fminf(sacc[mi][nj][hf * 2], 60.f)) : 0.f;
          float e1 = ((w >> (bp + 1)) & 1u) ? __expf(fminf(sacc[mi][nj][hf * 2 + 1], 60.f)) : 0.f;
          rs[mi * 2 + hf] += e0 + e1;
          *(float2*)(attnE + ((size_t)bh * L + qr) * L + kc * 128 + colL) = make_float2(e0, e1);
          *(uint32_t*)(sm + oES + (rl * 136 + colL) * 2) = packbf(e0, e1);
        }
    }
    __syncthreads();

    // O += E @ Vt
#pragma unroll
    for (int ks = 0; ks < 8; ks++) {
      uint32_t ea[2][4], vb[2][4];
#pragma unroll
      for (int mi = 0; mi < 2; mi++)
        ldm4(ea[mi], sb + oES + ((wy * 32 + mi * 16 + lr) * 136 + ks * 16 + lc) * 2);
#pragma unroll
      for (int ni = 0; ni < 2; ni++)
        ldm4(vb[ni], bV + ((wx * 32 + ni * 16 + lr) * 136 + ks * 16 + lc) * 2);
#pragma unroll
      for (int mi = 0; mi < 2; mi++)
#pragma unroll
        for (int nj = 0; nj < 4; nj++) {
          uint32_t bb2[2] = {vb[nj >> 1][nj & 1], vb[nj >> 1][(nj & 1) + 2]};
          mma_bf(acc_o[mi][nj], ea[mi], bb2);
        }
    }
    __syncthreads();
  }

  // rowsum reduce -> sinv
  float* ps = (float*)(sm + oPS);
  float* sinv = (float*)(sm + oSI);
#pragma unroll
  for (int j = 0; j < 4; j++) {
    float v = rs[j];
    v += __shfl_xor_sync(0xffffffffu, v, 1);
    v += __shfl_xor_sync(0xffffffffu, v, 2);
    if ((lane & 3) == 0) ps[wx * 128 + wy * 32 + (j >> 1) * 16 + (j & 1) * 8 + r0] = v;
  }
  __syncthreads();
  if (tid < 128) {
    float t = ps[tid] + ps[128 + tid];
    sinv[tid] = (t > 0.f) ? 1.f / t : 0.f;
  }
  __syncthreads();

  // O epilogue -> g_Obf (b,l,h*dv)
#pragma unroll
  for (int mi = 0; mi < 2; mi++)
#pragma unroll
    for (int hf = 0; hf < 2; hf++) {
      int rl = wy * 32 + mi * 16 + r0 + hf * 8;
      float iv = sinv[rl];
      int qr = q0 + rl;
#pragma unroll
      for (int nj = 0; nj < 4; nj++) {
        int dv = wx * 32 + nj * 8 + c0;
        *(uint32_t*)(g_Obf + ((size_t)b * L + qr) * 1024 + h * 64 + dv) =
            packbf(acc_o[mi][nj][hf * 2] * iv, acc_o[mi][nj][hf * 2 + 1] * iv);
      }
    }

  // fold attn normalization
  int rr = tid >> 1, sg = tid & 1;
  float iv2 = sinv[rr];
  float4* np = (float4*)(attnE + ((size_t)bh * L + q0 + rr) * L + sg * 1024);
#pragma unroll 4
  for (int i = 0; i < 256; i++) {
    float4 v = np[i];
    v.x *= iv2; v.y *= iv2; v.z *= iv2; v.w *= iv2;
    np[i] = v;
  }
}

// ---- LayerNorm ----
__global__ void __launch_bounds__(256) ln_kernel(const float* __restrict__ gamma,
    const float* __restrict__ beta, float* __restrict__ out) {
  const int row = blockIdx.x, tid = threadIdx.x;
  const float* x = g_X + (size_t)row * D;
  float4 v = *(const float4*)&x[tid * 4];
  float s = v.x + v.y + v.z + v.w;
  float s2 = v.x * v.x + v.y * v.y + v.z * v.z + v.w * v.w;
#pragma unroll
  for (int off = 16; off; off >>= 1) {
    s += __shfl_xor_sync(0xffffffffu, s, off);
    s2 += __shfl_xor_sync(0xffffffffu, s2, off);
  }
  __shared__ float ws[8], ws2[8], mean_s, rstd_s;
  int w = tid >> 5, lid = tid & 31;
  if (lid == 0) { ws[w] = s; ws2[w] = s2; }
  __syncthreads();
  if (tid == 0) {
    float S = 0.f, S2 = 0.f;
#pragma unroll
    for (int i = 0; i < 8; i++) { S += ws[i]; S2 += ws2[i]; }
    float mu = S * (1.f / D);
    mean_s = mu;
    rstd_s = rsqrtf(S2 * (1.f / D) - mu * mu + 1e-6f);
  }
  __syncthreads();
  float mu = mean_s, rstd = rstd_s;
  float4 g4 = *(const float4*)&gamma[tid * 4];
  float4 b4 = *(const float4*)&beta[tid * 4];
  *(float4*)&out[(size_t)row * D + tid * 4] = make_float4(
      (v.x - mu) * rstd * g4.x + b4.x, (v.y - mu) * rstd * g4.y + b4.y,
      (v.z - mu) * rstd * g4.z + b4.z, (v.w - mu) * rstd * g4.w + b4.w);
}

extern "C" void kernel_launch(void* const* d_in, const int* in_sizes, int n_in,
                              void* d_out, int out_size) {
  const float* q = (const float*)d_in[0];
  const float* k = (const float*)d_in[1];
  const float* v = (const float*)d_in[2];
  const int* mask = (const int*)d_in[3];
  const float* wq = (const float*)d_in[4];
  const float* wk = (const float*)d_in[5];
  const float* wv = (const float*)d_in[6];
  const float* wfc = (const float*)d_in[7];
  const float* lng = (const float*)d_in[8];
  const float* lnb = (const float*)d_in[9];
  (void)in_sizes; (void)n_in; (void)out_size;
  float* out = (float*)d_out;
  float* attn = out + OUT_ELEMS;

  __nv_bfloat16 *p_qh, *p_ql, *p_kh, *p_kl, *p_vbf;
  __nv_bfloat16 *p_wqh, *p_wql, *p_wkh, *p_wkl, *p_wvh, *p_wfh, *p_obf;
  uint32_t* p_mb;
  cudaGetSymbolAddress((void**)&p_qh, g_qh);
  cudaGetSymbolAddress((void**)&p_ql, g_ql);
  cudaGetSymbolAddress((void**)&p_kh, g_kh);
  cudaGetSymbolAddress((void**)&p_kl, g_kl);
  cudaGetSymbolAddress((void**)&p_vbf, g_vbf);
  cudaGetSymbolAddress((void**)&p_wqh, g_wqh);
  cudaGetSymbolAddress((void**)&p_wql, g_wql);
  cudaGetSymbolAddress((void**)&p_wkh, g_wkh);
  cudaGetSymbolAddress((void**)&p_wkl, g_wkl);
  cudaGetSymbolAddress((void**)&p_wvh, g_wvh);
  cudaGetSymbolAddress((void**)&p_wfh, g_wfh);
  cudaGetSymbolAddress((void**)&p_obf, g_Obf);
  cudaGetSymbolAddress((void**)&p_mb, g_mbits);

  cudaFuncSetAttribute(mmk<0>, cudaFuncAttributeMaxDynamicSharedMemorySize, 81920);
  cudaFuncSetAttribute(mmk<1>, cudaFuncAttributeMaxDynamicSharedMemorySize, 81920);
  cudaFuncSetAttribute(mmk<2>, cudaFuncAttributeMaxDynamicSharedMemorySize, 40960);
  cudaFuncSetAttribute(mmk<3>, cudaFuncAttributeMaxDynamicSharedMemorySize, 40960);
  cudaFuncSetAttribute(attn_tc, cudaFuncAttributeMaxDynamicSharedMemorySize, ATTN_SMEM);

  cvt_split<<<M * D / 1024, 256>>>(q, p_qh, p_ql);
  cvt_split<<<M * D / 1024, 256>>>(k, p_kh, p_kl);
  cvt1<<<M * D / 1024, 256>>>(v, p_vbf);
  wtrans<true><<<dim3(32, 32), 256>>>(wq, p_wqh, p_wql);
  wtrans<true><<<dim3(32, 32), 256>>>(wk, p_wkh, p_wkl);
  wtrans<false><<<dim3(32, 32), 256>>>(wv, p_wvh, nullptr);
  wtrans<false><<<dim3(32, 32), 256>>>(wfc, p_wfh, nullptr);
  mask_pack<<<(int)((size_t)B * L * 64 / 256), 256>>>(mask, p_mb);

  dim3 gg(D / 128, M / 128);
  mmk<0><<<gg, 256, 81920>>>(p_qh, p_ql, p_wqh, p_wql, nullptr);
  mmk<1><<<gg, 256, 81920>>>(p_kh, p_kl, p_wkh, p_wkl, nullptr);
  mmk<2><<<gg, 256, 40960>>>(p_vbf, nullptr, p_wvh, nullptr, nullptr);

  attn_tc<<<dim3(L / 128, H, B), 256, ATTN_SMEM>>>(attn);

  mmk<3><<<gg, 256, 40960>>>(p_obf, nullptr, p_wfh, nullptr, q);
  ln_kernel<<<M, 256>>>(lng, lnb, out);
}

// round 8
// speedup vs baseline: 1.9372x; 1.0468x over previous
#include <cuda_runtime.h>
#include <cuda_bf16.h>
#include <cstdint>

constexpr int B = 2, L = 2048, D = 1024, H = 16;
constexpr int M = B * L;
constexpr int OUT_ELEMS = B * L * D;

// ---- static device scratch ----
__device__ __align__(16) __nv_bfloat16 g_qh[M * D], g_ql[M * D];
__device__ __align__(16) __nv_bfloat16 g_kh[M * D], g_kl[M * D], g_vbf[M * D];
__device__ __align__(16) __nv_bfloat16 g_wqh[D * D], g_wql[D * D];
__device__ __align__(16) __nv_bfloat16 g_wkh[D * D], g_wkl[D * D];
__device__ __align__(16) __nv_bfloat16 g_wvh[D * D], g_wfh[D * D];
__device__ __align__(16) __nv_bfloat16 g_Qh[M * D], g_Ql[M * D];
__device__ __align__(16) __nv_bfloat16 g_Kh[M * D], g_Kl[M * D];
__device__ __align__(16) __nv_bfloat16 g_Vt[M * D];   // (b,h,dv,l)
__device__ __align__(16) __nv_bfloat16 g_Obf[M * D];  // (b,l,h*dv)
__device__ __align__(16) float g_X[M * D];
__device__ uint32_t g_mbits[(size_t)B * L * (L / 32)];

// ---- helpers (plain sm_103-legal PTX only) ----
__device__ __forceinline__ uint32_t s2u(const void* p) {
  uint32_t a;
  asm("{ .reg .u64 t; cvta.to.shared.u64 t, %1; cvt.u32.u64 %0, t; }" : "=r"(a) : "l"(p));
  return a;
}
#define CPA(dst, src) asm volatile("cp.async.cg.shared.global [%0], [%1], 16;" :: "r"(dst), "l"(src))
#define CPC() asm volatile("cp.async.commit_group;" ::: "memory")
#define CPW(n) asm volatile("cp.async.wait_group %0;" :: "n"(n) : "memory")
__device__ __forceinline__ void ldm4(uint32_t* r, uint32_t a) {
  asm volatile("ldmatrix.sync.aligned.m8n8.x4.shared.b16 {%0,%1,%2,%3}, [%4];"
               : "=r"(r[0]), "=r"(r[1]), "=r"(r[2]), "=r"(r[3]) : "r"(a));
}
__device__ __forceinline__ void mma_bf(float* d, const uint32_t* a, const uint32_t* b) {
  asm volatile(
      "mma.sync.aligned.m16n8k16.row.col.f32.bf16.bf16.f32 "
      "{%0,%1,%2,%3},{%4,%5,%6,%7},{%8,%9},{%0,%1,%2,%3};"
      : "+f"(d[0]), "+f"(d[1]), "+f"(d[2]), "+f"(d[3])
      : "r"(a[0]), "r"(a[1]), "r"(a[2]), "r"(a[3]), "r"(b[0]), "r"(b[1]));
}
__device__ __forceinline__ uint32_t packbf(float a, float b) {
  __nv_bfloat162 p = __halves2bfloat162(__float2bfloat16(a), __float2bfloat16(b));
  return *(uint32_t*)&p;
}

// ---- prep: q/k -> hi/lo bf16, v -> bf16 (one launch, grid.z selects) ----
__global__ void __launch_bounds__(256) cvt3(const float* __restrict__ q,
                                            const float* __restrict__ k,
                                            const float* __restrict__ v) {
  const int z = blockIdx.z;
  size_t i = (size_t)blockIdx.x * 1024 + threadIdx.x * 4;
  const float* in = (z == 0) ? q : (z == 1) ? k : v;
  float4 vv = *(const float4*)(in + i);
  if (z == 2) {
    *(uint2*)(g_vbf + i) = make_uint2(packbf(vv.x, vv.y), packbf(vv.z, vv.w));
    return;
  }
  __nv_bfloat16* hi = (z == 0) ? g_qh : g_kh;
  __nv_bfloat16* lo = (z == 0) ? g_ql : g_kl;
  float a[4] = {vv.x, vv.y, vv.z, vv.w};
  uint32_t ph[2], pl[2];
#pragma unroll
  for (int j = 0; j < 2; j++) {
    float x0 = a[j * 2], x1 = a[j * 2 + 1];
    __nv_bfloat16 h0 = __float2bfloat16(x0), h1 = __float2bfloat16(x1);
    ph[j] = packbf(x0, x1);
    pl[j] = packbf(x0 - __bfloat162float(h0), x1 - __bfloat162float(h1));
  }
  *(uint2*)(hi + i) = make_uint2(ph[0], ph[1]);
  *(uint2*)(lo + i) = make_uint2(pl[0], pl[1]);
}

// ---- weight transposes, grid.z = 4 (wq, wk split; wv, wfc single) ----
__global__ void __launch_bounds__(256) wtrans4(const float* __restrict__ wq,
                                               const float* __restrict__ wk,
                                               const float* __restrict__ wv,
                                               const float* __restrict__ wfc) {
  const int z = blockIdx.z;
  const float* w = (z == 0) ? wq : (z == 1) ? wk : (z == 2) ? wv : wfc;
  __nv_bfloat16* th = (z == 0) ? g_wqh : (z == 1) ? g_wkh : (z == 2) ? g_wvh : g_wfh;
  __nv_bfloat16* tl = (z == 0) ? g_wql : (z == 1) ? g_wkl : nullptr;
  __shared__ float t[32][33];
  int tx = threadIdx.x & 31, ty = threadIdx.x >> 5;
  int x0 = blockIdx.x * 32, y0 = blockIdx.y * 32;
#pragma unroll
  for (int i = 0; i < 4; i++)
    t[ty + i * 8][tx] = w[(size_t)(y0 + ty + i * 8) * D + x0 + tx];
  __syncthreads();
#pragma unroll
  for (int i = 0; i < 4; i++) {
    float v = t[tx][ty + i * 8];
    __nv_bfloat16 h = __float2bfloat16(v);
    size_t o = (size_t)(x0 + ty + i * 8) * D + y0 + tx;
    th[o] = h;
    if (tl) tl[o] = __float2bfloat16(v - __bfloat162float(h));
  }
}

__global__ void __launch_bounds__(256) mask_pack(const int* __restrict__ mask,
                                                 uint32_t* __restrict__ bits) {
  size_t w = (size_t)blockIdx.x * 256 + threadIdx.x;
  const int4* p = (const int4*)mask + w * 8;
  uint32_t v = 0;
#pragma unroll
  for (int i = 0; i < 8; i++) {
    int4 m = p[i];
    v |= (m.x != 0 ? 1u : 0u) << (i * 4);
    v |= (m.y != 0 ? 1u : 0u) << (i * 4 + 1);
    v |= (m.z != 0 ? 1u : 0u) << (i * 4 + 2);
    v |= (m.w != 0 ? 1u : 0u) << (i * 4 + 3);
  }
  bits[w] = v;
}

// ---- Q/K projection (split hi/lo), one launch, grid.z selects ----
__global__ void __launch_bounds__(256) mmQK() {
  extern __shared__ char sm[];
  const uint32_t sb = s2u(sm);
  const int z = blockIdx.z;
  const __nv_bfloat16* Ah = z ? g_kh : g_qh;
  const __nv_bfloat16* Al = z ? g_kl : g_ql;
  const __nv_bfloat16* Bh = z ? g_wkh : g_wqh;
  const __nv_bfloat16* Bl = z ? g_wkl : g_wql;
  __nv_bfloat16* DH = z ? g_Kh : g_Qh;
  __nv_bfloat16* DL = z ? g_Kl : g_Ql;
  const float sc = z ? 1.f : 0.125f;

  const int tid = threadIdx.x, lane = tid & 31, wid = tid >> 5;
  const int wy = wid >> 1, wx = wid & 1;
  const int m0 = blockIdx.y * 128, n0 = blockIdx.x * 128;
  const int lr = (lane & 7) + ((lane >> 3) & 1) * 8, lc = (lane >> 4) * 8;
  const int r0 = lane >> 2, c0 = 2 * (lane & 3);

  float acc[2][8][4];
#pragma unroll
  for (int i = 0; i < 2; i++)
#pragma unroll
    for (int j = 0; j < 8; j++)
#pragma unroll
      for (int t = 0; t < 4; t++) acc[i][j][t] = 0.f;

  auto issue = [&](int kc, int buf) {
    uint32_t bs = sb + buf * 40960;
#pragma unroll
    for (int i = 0; i < 2; i++) {
      int idx = tid + i * 256, row = idx >> 2, seg = idx & 3;
      uint32_t d0 = bs + row * 80 + seg * 16;
      size_t sa = (size_t)(m0 + row) * D + kc * 32 + seg * 8;
      size_t sg = (size_t)(n0 + row) * D + kc * 32 + seg * 8;
      CPA(d0, Ah + sa);
      CPA(d0 + 10240, Bh + sg);
      CPA(d0 + 20480, Al + sa);
      CPA(d0 + 30720, Bl + sg);
    }
    CPC();
  };

  issue(0, 0);
  for (int kc = 0; kc < 32; kc++) {
    if (kc < 31) { issue(kc + 1, (kc + 1) & 1); CPW(1); } else { CPW(0); }
    __syncthreads();
    uint32_t bs = sb + (kc & 1) * 40960;
#pragma unroll
    for (int ks = 0; ks < 2; ks++) {
      uint32_t aH[2][4], aL[2][4], bH[4][4], bL[4][4];
#pragma unroll
      for (int mi = 0; mi < 2; mi++) {
        uint32_t o = ((wy * 32 + mi * 16 + lr) * 40 + ks * 16 + lc) * 2;
        ldm4(aH[mi], bs + o);
        ldm4(aL[mi], bs + 20480 + o);
      }
#pragma unroll
      for (int ni = 0; ni < 4; ni++) {
        uint32_t o = ((wx * 64 + ni * 16 + lr) * 40 + ks * 16 + lc) * 2;
        ldm4(bH[ni], bs + 10240 + o);
        ldm4(bL[ni], bs + 30720 + o);
      }
#pragma unroll
      for (int mi = 0; mi < 2; mi++)
#pragma unroll
        for (int nj = 0; nj < 8; nj++) {
          uint32_t bb2[2] = {bH[nj >> 1][nj & 1], bH[nj >> 1][(nj & 1) + 2]};
          uint32_t bl2[2] = {bL[nj >> 1][nj & 1], bL[nj >> 1][(nj & 1) + 2]};
          mma_bf(acc[mi][nj], aH[mi], bb2);
          mma_bf(acc[mi][nj], aH[mi], bl2);
          mma_bf(acc[mi][nj], aL[mi], bb2);
        }
    }
    __syncthreads();
  }

#pragma unroll
  for (int mi = 0; mi < 2; mi++)
#pragma unroll
    for (int nj = 0; nj < 8; nj++)
#pragma unroll
      for (int hf = 0; hf < 2; hf++) {
        int mrow = m0 + wy * 32 + mi * 16 + r0 + hf * 8;
        int ncol = n0 + wx * 64 + nj * 8 + c0;
        float v0 = acc[mi][nj][hf * 2] * sc, v1 = acc[mi][nj][hf * 2 + 1] * sc;
        __nv_bfloat16 h0 = __float2bfloat16(v0), h1 = __float2bfloat16(v1);
        int bb = mrow >> 11, ll = mrow & 2047, hh = ncol >> 6, dk = ncol & 63;
        size_t o = (((size_t)bb * H + hh) * L + ll) * 64 + dk;
        *(uint32_t*)(DH + o) = packbf(v0, v1);
        *(uint32_t*)(DL + o) = packbf(v0 - __bfloat162float(h0), v1 - __bfloat162float(h1));
      }
}

// ---- HMMA GEMM (single bf16): MODE 2=V(transpose out) 3=FC(residual) ----
template <int MODE>
__global__ void __launch_bounds__(256) mmk(const __nv_bfloat16* __restrict__ Ah,
    const __nv_bfloat16* __restrict__ Bh, const float* __restrict__ resid) {
  extern __shared__ char sm[];
  const uint32_t sb = s2u(sm);
  const int tid = threadIdx.x, lane = tid & 31, wid = tid >> 5;
  const int wy = wid >> 1, wx = wid & 1;
  const int m0 = blockIdx.y * 128, n0 = blockIdx.x * 128;
  const int lr = (lane & 7) + ((lane >> 3) & 1) * 8, lc = (lane >> 4) * 8;
  const int r0 = lane >> 2, c0 = 2 * (lane & 3);

  float acc[2][8][4];
#pragma unroll
  for (int i = 0; i < 2; i++)
#pragma unroll
    for (int j = 0; j < 8; j++)
#pragma unroll
      for (int t = 0; t < 4; t++) acc[i][j][t] = 0.f;

  auto issue = [&](int kc, int buf) {
    uint32_t bs = sb + buf * 20480;
#pragma unroll
    for (int i = 0; i < 2; i++) {
      int idx = tid + i * 256, row = idx >> 2, seg = idx & 3;
      uint32_t d0 = bs + row * 80 + seg * 16;
      CPA(d0, Ah + (size_t)(m0 + row) * D + kc * 32 + seg * 8);
      CPA(d0 + 10240, Bh + (size_t)(n0 + row) * D + kc * 32 + seg * 8);
    }
    CPC();
  };

  issue(0, 0);
  for (int kc = 0; kc < 32; kc++) {
    if (kc < 31) { issue(kc + 1, (kc + 1) & 1); CPW(1); } else { CPW(0); }
    __syncthreads();
    uint32_t bs = sb + (kc & 1) * 20480;
#pragma unroll
    for (int ks = 0; ks < 2; ks++) {
      uint32_t aH[2][4], bH[4][4];
#pragma unroll
      for (int mi = 0; mi < 2; mi++)
        ldm4(aH[mi], bs + ((wy * 32 + mi * 16 + lr) * 40 + ks * 16 + lc) * 2);
#pragma unroll
      for (int ni = 0; ni < 4; ni++)
        ldm4(bH[ni], bs + 10240 + ((wx * 64 + ni * 16 + lr) * 40 + ks * 16 + lc) * 2);
#pragma unroll
      for (int mi = 0; mi < 2; mi++)
#pragma unroll
        for (int nj = 0; nj < 8; nj++) {
          uint32_t bb2[2] = {bH[nj >> 1][nj & 1], bH[nj >> 1][(nj & 1) + 2]};
          mma_bf(acc[mi][nj], aH[mi], bb2);
        }
    }
    __syncthreads();
  }

  if (MODE == 3) {
#pragma unroll
    for (int mi = 0; mi < 2; mi++)
#pragma unroll
      for (int nj = 0; nj < 8; nj++)
#pragma unroll
        for (int hf = 0; hf < 2; hf++) {
          int mrow = m0 + wy * 32 + mi * 16 + r0 + hf * 8;
          int ncol = n0 + wx * 64 + nj * 8 + c0;
          size_t o = (size_t)mrow * D + ncol;
          float2 rv = *(const float2*)(resid + o);
          *(float2*)(g_X + o) = make_float2(acc[mi][nj][hf * 2] + rv.x,
                                            acc[mi][nj][hf * 2 + 1] + rv.y);
        }
  } else {  // V: stage bf16 tile, transpose-write to g_Vt
    __nv_bfloat16* Cs = (__nv_bfloat16*)sm;
#pragma unroll
    for (int mi = 0; mi < 2; mi++)
#pragma unroll
      for (int nj = 0; nj < 8; nj++)
#pragma unroll
        for (int hf = 0; hf < 2; hf++) {
          int rl = wy * 32 + mi * 16 + r0 + hf * 8;
          int cl = wx * 64 + nj * 8 + c0;
          *(uint32_t*)(Cs + rl * 132 + cl) =
              packbf(acc[mi][nj][hf * 2], acc[mi][nj][hf * 2 + 1]);
        }
    __syncthreads();
    int bb = m0 >> 11, l0g = m0 & 2047;
#pragma unroll
    for (int rep = 0; rep < 8; rep++) {
      int col = rep * 16 + (tid >> 4);
      int ls = (tid & 15) * 8;
      int ncol = n0 + col, hh = ncol >> 6, dv = ncol & 63;
      union { unsigned short s[8]; uint4 u; } tmp;
#pragma unroll
      for (int j = 0; j < 8; j++) tmp.s[j] = ((unsigned short*)Cs)[(ls + j) * 132 + col];
      *(uint4*)(g_Vt + (((size_t)bb * H + hh) * 64 + dv) * L + l0g + ls) = tmp.u;
    }
  }
}

// ---- fused attention (HMMA, register-resident E for EV) ----
// smem: KH0[0,18432) KL0[18432,36864) VT0[36864,54272)
//       KH1[54272,72704) KL1[72704,91136) VT1[91136,108544)
//       RED[108544,143360) (Q-hi staging at start, fp32 O-reduction at end)
//       QL[143360,161792)  PS[161792,162816)  SI[162816,163328)
constexpr int oKH0 = 0, oKL0 = 18432, oVT0 = 36864;
constexpr int oKH1 = 54272, oKL1 = 72704, oVT1 = 91136;
constexpr int oRED = 108544;
constexpr int oQL = 143360;
constexpr int oPS = 161792, oSI = 162816;
constexpr int ATTN_SMEM = 163328;

__global__ void __launch_bounds__(256) attn_tc(float* __restrict__ attnE) {
  extern __shared__ char sm[];
  const uint32_t sb = s2u(sm);
  const int tid = threadIdx.x, lane = tid & 31, wid = tid >> 5;
  const int wy = wid >> 1, wx = wid & 1;
  const int b = blockIdx.z, h = blockIdx.y, q0 = blockIdx.x * 128, bh = b * H + h;
  const int lr = (lane & 7) + ((lane >> 3) & 1) * 8, lc = (lane >> 4) * 8;
  const int r0 = lane >> 2, c0 = 2 * (lane & 3);

  {  // stage Q: hi into RED area (row stride 144B), lo into QL
    const __nv_bfloat16* Qh = g_Qh + ((size_t)bh * L + q0) * 64;
    const __nv_bfloat16* Ql = g_Ql + ((size_t)bh * L + q0) * 64;
#pragma unroll
    for (int i = 0; i < 4; i++) {
      int idx = tid + i * 256, row = idx >> 3, seg = idx & 7;
      *(uint4*)(sm + oRED + row * 144 + seg * 16) = *(const uint4*)(Qh + (size_t)row * 64 + seg * 8);
      *(uint4*)(sm + oQL + row * 144 + seg * 16) = *(const uint4*)(Ql + (size_t)row * 64 + seg * 8);
    }
  }
  __syncthreads();

  auto issue = [&](int kc, int buf) {
    uint32_t oK = sb + (buf ? oKH1 : oKH0);
    uint32_t oKl = sb + (buf ? oKL1 : oKL0);
    uint32_t oV = sb + (buf ? oVT1 : oVT0);
    const __nv_bfloat16* Kh = g_Kh + ((size_t)bh * L + kc * 128) * 64;
    const __nv_bfloat16* Kl = g_Kl + ((size_t)bh * L + kc * 128) * 64;
    const __nv_bfloat16* Vt = g_Vt + (size_t)bh * 64 * L + kc * 128;
#pragma unroll
    for (int i = 0; i < 4; i++) {
      int idx = tid + i * 256, row = idx >> 3, seg = idx & 7;
      CPA(oK + row * 144 + seg * 16, Kh + (size_t)row * 64 + seg * 8);
      CPA(oKl + row * 144 + seg * 16, Kl + (size_t)row * 64 + seg * 8);
    }
#pragma unroll
    for (int i = 0; i < 4; i++) {
      int idx = tid + i * 256, row = idx >> 4, seg = idx & 15;
      CPA(oV + row * 272 + seg * 16, Vt + (size_t)row * L + seg * 8);
    }
    CPC();
  };
  issue(0, 0);

  uint32_t qh[2][4][4];
#pragma unroll
  for (int mi = 0; mi < 2; mi++)
#pragma unroll
    for (int ks = 0; ks < 4; ks++)
      ldm4(qh[mi][ks], sb + oRED + ((wy * 32 + mi * 16 + lr) * 72 + ks * 16 + lc) * 2);

  float acc_o[2][8][4];  // partial O over this warp's k-half, all 64 dv
#pragma unroll
  for (int i = 0; i < 2; i++)
#pragma unroll
    for (int j = 0; j < 8; j++)
#pragma unroll
      for (int t = 0; t < 4; t++) acc_o[i][j][t] = 0.f;
  float rs[4] = {0.f, 0.f, 0.f, 0.f};

  for (int kc = 0; kc < 16; kc++) {
    if (kc < 15) { issue(kc + 1, (kc + 1) & 1); CPW(1); } else { CPW(0); }
    __syncthreads();
    uint32_t bK = sb + ((kc & 1) ? oKH1 : oKH0);
    uint32_t bKl = sb + ((kc & 1) ? oKL1 : oKL0);
    uint32_t bV = sb + ((kc & 1) ? oVT1 : oVT0);

    float sacc[2][8][4];
#pragma unroll
    for (int i = 0; i < 2; i++)
#pragma unroll
      for (int j = 0; j < 8; j++)
#pragma unroll
        for (int t = 0; t < 4; t++) sacc[i][j][t] = 0.f;

#pragma unroll
    for (int ks = 0; ks < 4; ks++) {
      uint32_t bh4[4][4], bl4[4][4], ql4[2][4];
#pragma unroll
      for (int ni = 0; ni < 4; ni++) {
        uint32_t o = ((wx * 64 + ni * 16 + lr) * 72 + ks * 16 + lc) * 2;
        ldm4(bh4[ni], bK + o);
        ldm4(bl4[ni], bKl + o);
      }
#pragma unroll
      for (int mi = 0; mi < 2; mi++)
        ldm4(ql4[mi], sb + oQL + ((wy * 32 + mi * 16 + lr) * 72 + ks * 16 + lc) * 2);
#pragma unroll
      for (int mi = 0; mi < 2; mi++)
#pragma unroll
        for (int nj = 0; nj < 8; nj++) {
          uint32_t bb2[2] = {bh4[nj >> 1][nj & 1], bh4[nj >> 1][(nj & 1) + 2]};
          uint32_t bl2[2] = {bl4[nj >> 1][nj & 1], bl4[nj >> 1][(nj & 1) + 2]};
          mma_bf(sacc[mi][nj], qh[mi][ks], bb2);
          mma_bf(sacc[mi][nj], qh[mi][ks], bl2);
          mma_bf(sacc[mi][nj], ql4[mi], bb2);
        }
    }

    // epilogue: mask, exp, fp32->gmem, rowsum; e overwrites sacc
#pragma unroll
    for (int mi = 0; mi < 2; mi++) {
      uint32_t wm[2][2];
#pragma unroll
      for (int hf = 0; hf < 2; hf++) {
        int qr = q0 + wy * 32 + mi * 16 + r0 + hf * 8;
        size_t mo = ((size_t)b * L + qr) * 64 + kc * 4 + wx * 2;
        wm[hf][0] = g_mbits[mo];
        wm[hf][1] = g_mbits[mo + 1];
      }
#pragma unroll
      for (int nj = 0; nj < 8; nj++)
#pragma unroll
        for (int hf = 0; hf < 2; hf++) {
          int rl = wy * 32 + mi * 16 + r0 + hf * 8;
          int qr = q0 + rl;
          int colL = wx * 64 + nj * 8 + c0;
          uint32_t w = wm[hf][nj >> 2];
          int bp = (nj * 8 + c0) & 31;
          float e0 = ((w >> bp) & 1u) ? __expf(fminf(sacc[mi][nj][hf * 2], 60.f)) : 0.f;
          float e1 = ((w >> (bp + 1)) & 1u) ? __expf(fminf(sacc[mi][nj][hf * 2 + 1], 60.f)) : 0.f;
          rs[mi * 2 + hf] += e0 + e1;
          *(float2*)(attnE + ((size_t)bh * L + qr) * L + kc * 128 + colL) = make_float2(e0, e1);
          sacc[mi][nj][hf * 2] = e0;
          sacc[mi][nj][hf * 2 + 1] = e1;
        }
    }

    // O += E @ Vt — E fragments straight from registers (S C-frag == EV A-frag)
#pragma unroll
    for (int kt = 0; kt < 4; kt++) {
      uint32_t vb[4][4];
#pragma unroll
      for (int ni = 0; ni < 4; ni++)
        ldm4(vb[ni], bV + ((ni * 16 + lr) * 136 + wx * 64 + kt * 16 + lc) * 2);
#pragma unroll
      for (int mi = 0; mi < 2; mi++) {
        uint32_t ae[4] = {packbf(sacc[mi][2 * kt][0], sacc[mi][2 * kt][1]),
                          packbf(sacc[mi][2 * kt][2], sacc[mi][2 * kt][3]),
                          packbf(sacc[mi][2 * kt + 1][0], sacc[mi][2 * kt + 1][1]),
                          packbf(sacc[mi][2 * kt + 1][2], sacc[mi][2 * kt + 1][3])};
#pragma unroll
        for (int njO = 0; njO < 8; njO++) {
          uint32_t bb2[2] = {vb[njO >> 1][njO & 1], vb[njO >> 1][(njO & 1) + 2]};
          mma_bf(acc_o[mi][njO], ae, bb2);
        }
      }
    }
    // REQUIRED: all warps must finish reading this buffer pair before anyone
    // issues the next-next chunk's cp.async into it (double buffer).
    __syncthreads();
  }

  // rowsum reduce -> sinv
  float* ps = (float*)(sm + oPS);
  float* sinv = (float*)(sm + oSI);
#pragma unroll
  for (int j = 0; j < 4; j++) {
    float v = rs[j];
    v += __shfl_xor_sync(0xffffffffu, v, 1);
    v += __shfl_xor_sync(0xffffffffu, v, 2);
    if ((lane & 3) == 0) ps[wx * 128 + wy * 32 + (j >> 1) * 16 + (j & 1) * 8 + r0] = v;
  }
  __syncthreads();
  if (tid < 128) {
    float t = ps[tid] + ps[128 + tid];
    sinv[tid] = (t > 0.f) ? 1.f / t : 0.f;
  }
  __syncthreads();

  // cross-wx O reduction via RED (Q staging long dead), then normalized store
  float* red = (float*)(sm + oRED);
  if (wx == 1) {
#pragma unroll
    for (int mi = 0; mi < 2; mi++)
#pragma unroll
      for (int hf = 0; hf < 2; hf++) {
        int rl = wy * 32 + mi * 16 + r0 + hf * 8;
#pragma unroll
        for (int njO = 0; njO < 8; njO++)
          *(float2*)&red[rl * 68 + njO * 8 + c0] =
              make_float2(acc_o[mi][njO][hf * 2], acc_o[mi][njO][hf * 2 + 1]);
      }
  }
  __syncthreads();
  if (wx == 0) {
#pragma unroll
    for (int mi = 0; mi < 2; mi++)
#pragma unroll
      for (int hf = 0; hf < 2; hf++) {
        int rl = wy * 32 + mi * 16 + r0 + hf * 8;
        float iv = sinv[rl];
        int qr = q0 + rl;
#pragma unroll
        for (int njO = 0; njO < 8; njO++) {
          float2 p = *(float2*)&red[rl * 68 + njO * 8 + c0];
          *(uint32_t*)(g_Obf + ((size_t)b * L + qr) * 1024 + h * 64 + njO * 8 + c0) =
              packbf((acc_o[mi][njO][hf * 2] + p.x) * iv,
                     (acc_o[mi][njO][hf * 2 + 1] + p.y) * iv);
        }
      }
  }

  // fold attn normalization (re-read + scale)
  int rr = tid >> 1, sg = tid & 1;
  float iv2 = sinv[rr];
  float4* np = (float4*)(attnE + ((size_t)bh * L + q0 + rr) * L + sg * 1024);
#pragma unroll 4
  for (int i = 0; i < 256; i++) {
    float4 v = np[i];
    v.x *= iv2; v.y *= iv2; v.z *= iv2; v.w *= iv2;
    np[i] = v;
  }
}

// ---- LayerNorm ----
__global__ void __launch_bounds__(256) ln_kernel(const float* __restrict__ gamma,
    const float* __restrict__ beta, float* __restrict__ out) {
  const int row = blockIdx.x, tid = threadIdx.x;
  const float* x = g_X + (size_t)row * D;
  float4 v = *(const float4*)&x[tid * 4];
  float s = v.x + v.y + v.z + v.w;
  float s2 = v.x * v.x + v.y * v.y + v.z * v.z + v.w * v.w;
#pragma unroll
  for (int off = 16; off; off >>= 1) {
    s += __shfl_xor_sync(0xffffffffu, s, off);
    s2 += __shfl_xor_sync(0xffffffffu, s2, off);
  }
  __shared__ float ws[8], ws2[8], mean_s, rstd_s;
  int w = tid >> 5, lid = tid & 31;
  if (lid == 0) { ws[w] = s; ws2[w] = s2; }
  __syncthreads();
  if (tid == 0) {
    float S = 0.f, S2 = 0.f;
#pragma unroll
    for (int i = 0; i < 8; i++) { S += ws[i]; S2 += ws2[i]; }
    float mu = S * (1.f / D);
    mean_s = mu;
    rstd_s = rsqrtf(S2 * (1.f / D) - mu * mu + 1e-6f);
  }
  __syncthreads();
  float mu = mean_s, rstd = rstd_s;
  float4 g4 = *(const float4*)&gamma[tid * 4];
  float4 b4 = *(const float4*)&beta[tid * 4];
  *(float4*)&out[(size_t)row * D + tid * 4] = make_float4(
      (v.x - mu) * rstd * g4.x + b4.x, (v.y - mu) * rstd * g4.y + b4.y,
      (v.z - mu) * rstd * g4.z + b4.z, (v.w - mu) * rstd * g4.w + b4.w);
}

extern "C" void kernel_launch(void* const* d_in, const int* in_sizes, int n_in,
                              void* d_out, int out_size) {
  const float* q = (const float*)d_in[0];
  const float* k = (const float*)d_in[1];
  const float* v = (const float*)d_in[2];
  const int* mask = (const int*)d_in[3];
  const float* wq = (const float*)d_in[4];
  const float* wk = (const float*)d_in[5];
  const float* wv = (const float*)d_in[6];
  const float* wfc = (const float*)d_in[7];
  const float* lng = (const float*)d_in[8];
  const float* lnb = (const float*)d_in[9];
  (void)in_sizes; (void)n_in; (void)out_size;
  float* out = (float*)d_out;
  float* attn = out + OUT_ELEMS;

  __nv_bfloat16 *p_vbf, *p_wvh, *p_wfh, *p_obf;
  uint32_t* p_mb;
  cudaGetSymbolAddress((void**)&p_vbf, g_vbf);
  cudaGetSymbolAddress((void**)&p_wvh, g_wvh);
  cudaGetSymbolAddress((void**)&p_wfh, g_wfh);
  cudaGetSymbolAddress((void**)&p_obf, g_Obf);
  cudaGetSymbolAddress((void**)&p_mb, g_mbits);

  cudaFuncSetAttribute(mmQK, cudaFuncAttributeMaxDynamicSharedMemorySize, 81920);
  cudaFuncSetAttribute(mmk<2>, cudaFuncAttributeMaxDynamicSharedMemorySize, 40960);
  cudaFuncSetAttribute(mmk<3>, cudaFuncAttributeMaxDynamicSharedMemorySize, 40960);
  cudaFuncSetAttribute(attn_tc, cudaFuncAttributeMaxDynamicSharedMemorySize, ATTN_SMEM);

  // launch order chosen so attn_tc is launch index 5 (= ncu -s 5 -c 1 slot)
  cvt3<<<dim3(M * D / 1024, 1, 3), 256>>>(q, k, v);                       // 0
  wtrans4<<<dim3(32, 32, 4), 256>>>(wq, wk, wv, wfc);                     // 1
  mask_pack<<<(int)((size_t)B * L * 64 / 256), 256>>>(mask, p_mb);        // 2
  mmQK<<<dim3(8, 32, 2), 256, 81920>>>();                                 // 3
  mmk<2><<<dim3(8, 32), 256, 40960>>>(p_vbf, p_wvh, nullptr);             // 4
  attn_tc<<<dim3(L / 128, H, B), 256, ATTN_SMEM>>>(attn);                 // 5
  mmk<3><<<dim3(8, 32), 256, 40960>>>(p_obf, p_wfh, q);                   // 6
  ln_kernel<<<M, 256>>>(lng, lnb, out);                                   // 7
}